// round 6
// baseline (speedup 1.0000x reference)
#include <cuda_runtime.h>
#include <cuda_fp16.h>
#include <cstdint>

// Problem constants
constexpr int CB  = 2;     // batch
constexpr int CL  = 4096;  // seq len
constexpr int CDM = 768;   // d_model
constexpr int CDI = 1536;  // d_inner
constexpr int CN  = 16;    // state dim
constexpr int CR  = 48;    // dt rank
constexpr int CK  = 4;     // conv width
constexpr int CPROJ = CR + 2*CN; // 80

// ---------------------------------------------------------------------------
// Scratch (device globals; no runtime allocation allowed)
// ---------------------------------------------------------------------------
__device__ float g_xz[CB * 2 * CDI * CL];        // (b, e, l)
__device__ float g_dbl[2][CB * CL * CPROJ];      // per dir, (b*L, 80): dt|B|C
__device__ float g_delta[2][CB * CL * CDI];      // per dir, post-softplus
__device__ float g_y[2][CB * CL * CDI];          // per dir, scan out (+D*x)

// fp16 operands for tensor GEMMs
__device__ __half g_hid_h[CB*CL*CDM], g_hid_l[CB*CL*CDM];  // hidden hi/lo (split side)
__device__ __half g_w1[2*CDI*CDM];                          // in_proj W (single)
__device__ __half g_w2[CDM*CDI];                            // out_proj W (single)
__device__ __half g_wx[2][128*CDI];                         // xproj W padded 80->128 (single)
__device__ __half g_xth[2][CB*CL*CDI], g_xtl[2][CB*CL*CDI]; // conv out hi/lo (split side)
__device__ __half g_cmb_h[CB*CL*CDI],  g_cmb_l[CB*CL*CDI];  // gated sum hi/lo (split side)

// ---------------------------------------------------------------------------
// PTX helpers
// ---------------------------------------------------------------------------
__device__ __forceinline__ uint32_t smem_u32(const void* p) {
    uint32_t a;
    asm("{ .reg .u64 t; cvta.to.shared.u64 t, %1; cvt.u32.u64 %0, t; }" : "=r"(a) : "l"(p));
    return a;
}
__device__ __forceinline__ uint32_t sw128(uint32_t b) { return b ^ ((b >> 3) & 0x70); }

__device__ __forceinline__ void ldsm4(uint32_t addr, uint32_t r[4]) {
    asm volatile("ldmatrix.sync.aligned.m8n8.x4.shared.b16 {%0,%1,%2,%3}, [%4];"
        : "=r"(r[0]), "=r"(r[1]), "=r"(r[2]), "=r"(r[3]) : "r"(addr));
}
__device__ __forceinline__ void mma_f16(float* d, const uint32_t* a, uint32_t b0, uint32_t b1) {
    asm volatile("mma.sync.aligned.m16n8k16.row.col.f32.f16.f16.f32 "
        "{%0,%1,%2,%3}, {%4,%5,%6,%7}, {%8,%9}, {%0,%1,%2,%3};"
        : "+f"(d[0]), "+f"(d[1]), "+f"(d[2]), "+f"(d[3])
        : "r"(a[0]), "r"(a[1]), "r"(a[2]), "r"(a[3]), "r"(b0), "r"(b1));
}
__device__ __forceinline__ void cp16(uint32_t s, const void* g) {
    asm volatile("cp.async.ca.shared.global [%0], [%1], 16;" :: "r"(s), "l"(g));
}

// ---------------------------------------------------------------------------
// 2-term fp16 tensor GEMM:  C[m,n] = sum_k A[m,k]*B[n,k]  (fp32 out)
// Exactly one operand side is split (hi+lo fp16); the other is single fp16.
// CTA tile 128x128, BK=64, 2-stage cp.async ring, 96KB smem -> 2 CTA/SM.
// Stage (48KB): A-hi 16K | split-lo 16K | B-hi 16K.
// ---------------------------------------------------------------------------
constexpr int GF_STAGE = 49152;
constexpr int GF_SMEM  = 2 * GF_STAGE;   // 98304 B

template <int SPLIT_A>
__global__ void __launch_bounds__(256, 2) gemm_f16_kernel(
    const __half* __restrict__ Ah, const __half* __restrict__ Xl,  // Xl = Al or Bl
    const __half* __restrict__ Bh,
    float* __restrict__ C, int Nout, int Kd,
    long long strideA, long long strideB, long long strideC, int NC)
{
    extern __shared__ __align__(1024) char smem[];
    const uint32_t su = smem_u32(smem);
    Ah += (size_t)blockIdx.z * strideA;
    Bh += (size_t)blockIdx.z * strideB;
    Xl += (size_t)blockIdx.z * (SPLIT_A ? strideA : strideB);
    C  += (size_t)blockIdx.z * strideC;
    const int bm = blockIdx.y * 128;
    const int bn = blockIdx.x * 128;
    const int tid  = threadIdx.x;
    const int wid  = tid >> 5;
    const int lane = tid & 31;

    const int prow = tid >> 3;          // 0..31 -> x4 gives 128 rows
    const int pkc  = tid & 7;           // 16B chunk within 128B row
    auto issue = [&](int c) {
        const uint32_t sb = su + (uint32_t)(c & 1) * GF_STAGE;
        const int k0 = c * 64;
#pragma unroll
        for (int i = 0; i < 4; ++i) {
            const int row = prow + i * 32;
            const uint32_t off = sw128((uint32_t)(row * 128 + pkc * 16));
            const size_t ga = (size_t)(bm + row) * Kd + k0 + pkc * 8;
            const size_t gb = (size_t)(bn + row) * Kd + k0 + pkc * 8;
            cp16(sb + off,         Ah + ga);
            cp16(sb + 16384 + off, Xl + (SPLIT_A ? ga : gb));
            cp16(sb + 32768 + off, Bh + gb);
        }
        asm volatile("cp.async.commit_group;" ::: "memory");
    };

    // warp tiling: 4x2 warps, warp tile 32 (m) x 64 (n)
    const int m0 = (wid & 3) * 32;
    const int n0 = (wid >> 2) * 64;
    const int g    = lane >> 3;
    const int lr   = lane & 7;
    const int lrow = (g & 1) * 8 + lr;
    const int lkb  = (g >> 1) * 16;

    float acc[2][8][4] = {};

    issue(0); issue(1);

    for (int c = 0; c < NC; ++c) {
        asm volatile("cp.async.wait_group 1;" ::: "memory");
        __syncthreads();
        const uint32_t sb = su + (uint32_t)(c & 1) * GF_STAGE;
#pragma unroll
        for (int kk = 0; kk < 4; ++kk) {
            uint32_t ah[2][4], al[2][4];
#pragma unroll
            for (int mt = 0; mt < 2; ++mt) {
                uint32_t off = sw128((uint32_t)((m0 + mt*16 + lrow) * 128 + kk*32 + lkb));
                ldsm4(sb + off, ah[mt]);
                if (SPLIT_A) ldsm4(sb + 16384 + off, al[mt]);
            }
#pragma unroll
            for (int np = 0; np < 4; ++np) {
                uint32_t boff = sw128((uint32_t)((n0 + np*16 + lrow) * 128 + kk*32 + lkb));
                uint32_t bh[4], bl[4];
                ldsm4(sb + 32768 + boff, bh);
                if (!SPLIT_A) ldsm4(sb + 16384 + boff, bl);
#pragma unroll
                for (int mt = 0; mt < 2; ++mt) {
                    if (SPLIT_A) {
                        mma_f16(acc[mt][2*np],   ah[mt], bh[0], bh[2]);
                        mma_f16(acc[mt][2*np],   al[mt], bh[0], bh[2]);
                        mma_f16(acc[mt][2*np+1], ah[mt], bh[1], bh[3]);
                        mma_f16(acc[mt][2*np+1], al[mt], bh[1], bh[3]);
                    } else {
                        mma_f16(acc[mt][2*np],   ah[mt], bh[0], bh[2]);
                        mma_f16(acc[mt][2*np],   ah[mt], bl[0], bl[2]);
                        mma_f16(acc[mt][2*np+1], ah[mt], bh[1], bh[3]);
                        mma_f16(acc[mt][2*np+1], ah[mt], bl[1], bl[3]);
                    }
                }
            }
        }
        __syncthreads();
        if (c + 2 < NC) issue(c + 2);
        else asm volatile("cp.async.commit_group;" ::: "memory");
    }

    // epilogue
    const int er = lane >> 2;
    const int ec = (lane & 3) * 2;
#pragma unroll
    for (int mt = 0; mt < 2; ++mt) {
#pragma unroll
        for (int nt = 0; nt < 8; ++nt) {
            const int row = bm + m0 + mt*16 + er;
            const int col = bn + n0 + nt*8 + ec;
            if (col < Nout) {
                float2 lo = { acc[mt][nt][0], acc[mt][nt][1] };
                float2 hi = { acc[mt][nt][2], acc[mt][nt][3] };
                *(float2*)(C + (size_t)row * Nout + col)       = lo;
                *(float2*)(C + (size_t)(row + 8) * Nout + col) = hi;
            }
        }
    }
}

// ---------------------------------------------------------------------------
// fp32 -> fp16 hi/lo splitter and single-fp16 converter (grid-stride, float4)
// ---------------------------------------------------------------------------
__global__ void split2_kernel(const float* __restrict__ s,
                              __half* __restrict__ h, __half* __restrict__ l, int n4)
{
    for (int i = blockIdx.x * blockDim.x + threadIdx.x; i < n4;
         i += gridDim.x * blockDim.x) {
        float4 v = ((const float4*)s)[i];
        __half hx = __float2half_rn(v.x), hy = __float2half_rn(v.y);
        __half hz = __float2half_rn(v.z), hw = __float2half_rn(v.w);
        __half lx = __float2half_rn(v.x - __half2float(hx));
        __half ly = __float2half_rn(v.y - __half2float(hy));
        __half lz = __float2half_rn(v.z - __half2float(hz));
        __half lw = __float2half_rn(v.w - __half2float(hw));
        __half2 h01 = __halves2half2(hx, hy), h23 = __halves2half2(hz, hw);
        __half2 l01 = __halves2half2(lx, ly), l23 = __halves2half2(lz, lw);
        ((uint2*)h)[i] = make_uint2(*(uint32_t*)&h01, *(uint32_t*)&h23);
        ((uint2*)l)[i] = make_uint2(*(uint32_t*)&l01, *(uint32_t*)&l23);
    }
}

__global__ void tof16_kernel(const float* __restrict__ s, __half* __restrict__ h, int n4)
{
    for (int i = blockIdx.x * blockDim.x + threadIdx.x; i < n4;
         i += gridDim.x * blockDim.x) {
        float4 v = ((const float4*)s)[i];
        __half2 h01 = __halves2half2(__float2half_rn(v.x), __float2half_rn(v.y));
        __half2 h23 = __halves2half2(__float2half_rn(v.z), __float2half_rn(v.w));
        ((uint2*)h)[i] = make_uint2(*(uint32_t*)&h01, *(uint32_t*)&h23);
    }
}

// xproj weights: pad 80 -> 128 rows (zeros), single fp16, both dirs.
__global__ void padw_kernel(const float* __restrict__ wf, const float* __restrict__ wb)
{
    const int total4 = 2 * 128 * CDI / 4;
    for (int i = blockIdx.x * blockDim.x + threadIdx.x; i < total4;
         i += gridDim.x * blockDim.x) {
        int e = i * 4;
        int dir = e / (128 * CDI);
        int rem = e - dir * 128 * CDI;
        int row = rem / CDI;
        int k   = rem - row * CDI;
        float4 v = {0.f, 0.f, 0.f, 0.f};
        const float* W = dir ? wb : wf;
        if (row < CPROJ) v = *(const float4*)(W + (size_t)row * CDI + k);
        __half2 h01 = __halves2half2(__float2half_rn(v.x), __float2half_rn(v.y));
        __half2 h23 = __halves2half2(__float2half_rn(v.z), __float2half_rn(v.w));
        ((uint2*)&g_wx[0][0])[i] = make_uint2(*(uint32_t*)&h01, *(uint32_t*)&h23);
    }
}

// ---------------------------------------------------------------------------
// Depthwise causal conv (K=4) + bias + SiLU, transpose to (b,t,d).
// ---------------------------------------------------------------------------
__global__ void __launch_bounds__(256) conv_silu_kernel(
    const float* __restrict__ cw_f, const float* __restrict__ cb_f,
    const float* __restrict__ cw_b, const float* __restrict__ cb_b)
{
    const int t0 = blockIdx.x * 128;
    const int d0 = blockIdx.y * 32;
    const int b   = blockIdx.z & 1;
    const int dir = blockIdx.z >> 1;

    __shared__ float xs[32][133];

    const float* xbase = g_xz + ((size_t)b * (2*CDI) + d0) * CL;
    const int base = (dir == 0) ? (t0 - 3) : (CL - 128 - t0);

    const int lane = threadIdx.x & 31;
    const int wy   = threadIdx.x >> 5;
    for (int d = wy; d < 32; d += 8) {
        const float* row = xbase + (size_t)d * CL;
        for (int i = lane; i < 131; i += 32) {
            int u = base + i;
            xs[d][i] = (u >= 0 && u < CL) ? row[u] : 0.f;
        }
    }
    __syncthreads();

    const int d  = threadIdx.x & 31;
    const int sg = threadIdx.x >> 5;
    const float* cw = dir ? cw_b : cw_f;
    const float* cb = dir ? cb_b : cb_f;
    const float w0 = cw[(d0+d)*CK + 0];
    const float w1 = cw[(d0+d)*CK + 1];
    const float w2 = cw[(d0+d)*CK + 2];
    const float w3 = cw[(d0+d)*CK + 3];
    const float bias = cb[d0+d];

    __half* oh = g_xth[dir] + (size_t)b * CL * CDI;
    __half* ol = g_xtl[dir] + (size_t)b * CL * CDI;
#pragma unroll
    for (int q = 0; q < 16; ++q) {
        int s = sg + 8*q;
        float v;
        if (dir == 0) {
            v = w0*xs[d][s] + w1*xs[d][s+1] + w2*xs[d][s+2] + w3*xs[d][s+3] + bias;
        } else {
            v = w3*xs[d][127-s] + w2*xs[d][127-s+1] + w1*xs[d][127-s+2] + w0*xs[d][127-s+3] + bias;
        }
        float sv = v / (1.f + __expf(-v));
        size_t idx = (size_t)(t0 + s) * CDI + d0 + d;
        __half hb = __float2half_rn(sv);
        oh[idx] = hb;
        ol[idx] = __float2half_rn(sv - __half2float(hb));
    }
}

// ---------------------------------------------------------------------------
// dtproj + softplus — software-pipelined k-loop (prefetch k+1 operands into
// registers before the 32 FFMAs of k, breaking the LDS->FFMA stall chain).
// ---------------------------------------------------------------------------
__device__ __forceinline__ float softplus_f(float v) {
    return (v > 20.f) ? v : log1pf(__expf(v));
}

__global__ void __launch_bounds__(256) dtproj_kernel(
    const float* __restrict__ dtw_f, const float* __restrict__ dtb_f,
    const float* __restrict__ dtw_b, const float* __restrict__ dtb_b)
{
    const int dir = blockIdx.z;
    const float* W    = dir ? dtw_b : dtw_f;
    const float* bias = dir ? dtb_b : dtb_f;
    const float* DT = g_dbl[dir];
    float* O = g_delta[dir];

    const int r0 = blockIdx.x * 64;
    const int d0 = blockIdx.y * 128;

    __shared__ __align__(16) float Ts[48][64];
    __shared__ __align__(16) float Ws2[48][128];

    const int tid = threadIdx.x;
#pragma unroll
    for (int p = 0; p < 3; ++p) {
        int q = tid + p*256;
        int rr = q / 12, kk = (q % 12) * 4;
        float4 v = *(const float4*)(DT + (size_t)(r0+rr)*CPROJ + kk);
        Ts[kk+0][rr]=v.x; Ts[kk+1][rr]=v.y; Ts[kk+2][rr]=v.z; Ts[kk+3][rr]=v.w;
    }
#pragma unroll
    for (int p = 0; p < 6; ++p) {
        int q = tid + p*256;
        int dd = q / 12, kk = (q % 12) * 4;
        float4 v = *(const float4*)(W + (size_t)(d0+dd)*CR + kk);
        Ws2[kk+0][dd]=v.x; Ws2[kk+1][dd]=v.y; Ws2[kk+2][dd]=v.z; Ws2[kk+3][dd]=v.w;
    }
    __syncthreads();

    const int tx = tid & 31;
    const int ty = tid >> 5;
    float acc[8][4] = {};

    float4 a0 = *(const float4*)&Ts[0][ty*8];
    float4 a1 = *(const float4*)&Ts[0][ty*8+4];
    float4 w  = *(const float4*)&Ws2[0][tx*4];
#pragma unroll
    for (int k = 0; k < 48; ++k) {
        float4 na0, na1, nw;
        if (k + 1 < 48) {
            na0 = *(const float4*)&Ts[k+1][ty*8];
            na1 = *(const float4*)&Ts[k+1][ty*8+4];
            nw  = *(const float4*)&Ws2[k+1][tx*4];
        }
        float a[8]  = {a0.x,a0.y,a0.z,a0.w,a1.x,a1.y,a1.z,a1.w};
        float ww[4] = {w.x, w.y, w.z, w.w};
#pragma unroll
        for (int i = 0; i < 8; ++i)
#pragma unroll
            for (int j = 0; j < 4; ++j)
                acc[i][j] = fmaf(a[i], ww[j], acc[i][j]);
        a0 = na0; a1 = na1; w = nw;
    }

    const int tx4 = tx*4;
    float b0 = bias[d0+tx4+0], b1 = bias[d0+tx4+1], b2 = bias[d0+tx4+2], b3 = bias[d0+tx4+3];
#pragma unroll
    for (int i = 0; i < 8; ++i) {
        float4 v;
        v.x = softplus_f(acc[i][0] + b0);
        v.y = softplus_f(acc[i][1] + b1);
        v.z = softplus_f(acc[i][2] + b2);
        v.w = softplus_f(acc[i][3] + b3);
        *(float4*)(O + (size_t)(r0 + ty*8 + i)*CDI + d0 + tx4) = v;
    }
}

// ---------------------------------------------------------------------------
// Selective scan (warp = 2 channels x 16 states).
// Packed staging: sdd = (dt, dt*x) float2, sbc = (B, C) float2, sxD = x*D.
// Inner step: 2x LDS.64 + exp + 2 flops + 4 shfl-add + predicated D-add/store.
// ---------------------------------------------------------------------------
__global__ void __launch_bounds__(256) scan_kernel(
    const float* __restrict__ Alog_f, const float* __restrict__ Dv_f,
    const float* __restrict__ Alog_b, const float* __restrict__ Dv_b)
{
    const int dir = blockIdx.z;
    const int b   = blockIdx.y;
    const int d0  = blockIdx.x * 16;

    const float* Alog = dir ? Alog_b : Alog_f;
    const float* Dvec = dir ? Dv_b   : Dv_f;
    const float* delta = g_delta[dir] + (size_t)b * CL * CDI;
    const __half* xth  = g_xth[dir]   + (size_t)b * CL * CDI;
    const __half* xtl  = g_xtl[dir]   + (size_t)b * CL * CDI;
    const float* dbl   = g_dbl[dir]   + (size_t)b * CL * CPROJ;
    float* yout        = g_y[dir]     + (size_t)b * CL * CDI;

    __shared__ __align__(16) float2 sdd[64][16];   // (dt, dt*x)
    __shared__ __align__(16) float2 sbc[64][16];   // (B, C)
    __shared__ __align__(16) float  sxD[64][16];   // x * D[d]

    const int tid  = threadIdx.x;
    const int lane = tid & 31;
    const int wid  = tid >> 5;
    const int half = lane >> 4;
    const int n    = lane & 15;
    const int ch   = wid*2 + half;
    const int d    = d0 + ch;

    const float Aval = -__expf(Alog[d*CN + n]);
    float h = 0.f;

    const int li = tid >> 2;          // staging row 0..63
    const int lj = (tid & 3) * 4;     // staging cols 0,4,8,12

    // per-staging-thread D values (loaded once)
    float rDv[4];
#pragma unroll
    for (int j = 0; j < 4; ++j) rDv[j] = Dvec[d0 + lj + j];

    float4 rd, rB, rC, rx;
    auto LD = [&](int t0) {
        rd = *(const float4*)(delta + (size_t)(t0+li)*CDI + d0 + lj);
        uint2 xh = *(const uint2*)(xth + (size_t)(t0+li)*CDI + d0 + lj);
        uint2 xl = *(const uint2*)(xtl + (size_t)(t0+li)*CDI + d0 + lj);
        __half2 h01 = *(__half2*)&xh.x, h23 = *(__half2*)&xh.y;
        __half2 l01 = *(__half2*)&xl.x, l23 = *(__half2*)&xl.y;
        float2 fh01 = __half22float2(h01), fh23 = __half22float2(h23);
        float2 fl01 = __half22float2(l01), fl23 = __half22float2(l23);
        rx.x = fh01.x + fl01.x; rx.y = fh01.y + fl01.y;
        rx.z = fh23.x + fl23.x; rx.w = fh23.y + fl23.y;
        rB = *(const float4*)(dbl + (size_t)(t0+li)*CPROJ + CR + lj);
        rC = *(const float4*)(dbl + (size_t)(t0+li)*CPROJ + CR + CN + lj);
    };
    LD(0);

    const int NCH = CL / 64;
    for (int c = 0; c < NCH; ++c) {
        __syncthreads();
        {
            float dt4[4] = {rd.x, rd.y, rd.z, rd.w};
            float x4[4]  = {rx.x, rx.y, rx.z, rx.w};
            float B4[4]  = {rB.x, rB.y, rB.z, rB.w};
            float C4[4]  = {rC.x, rC.y, rC.z, rC.w};
#pragma unroll
            for (int j = 0; j < 4; ++j) {
                sdd[li][lj+j] = make_float2(dt4[j], dt4[j] * x4[j]);
                sbc[li][lj+j] = make_float2(B4[j], C4[j]);
                sxD[li][lj+j] = x4[j] * rDv[j];
            }
        }
        __syncthreads();
        if (c + 1 < NCH) LD((c+1) * 64);

        const int tbase = c * 64;
#pragma unroll 8
        for (int s = 0; s < 64; ++s) {
            float2 ddt = sdd[s][ch];
            float2 bc  = sbc[s][n];
            float a = __expf(ddt.x * Aval);
            h = fmaf(a, h, ddt.y * bc.x);
            float p = h * bc.y;
            p += __shfl_xor_sync(0xffffffffu, p, 8);
            p += __shfl_xor_sync(0xffffffffu, p, 4);
            p += __shfl_xor_sync(0xffffffffu, p, 2);
            p += __shfl_xor_sync(0xffffffffu, p, 1);
            if (n == 0)
                yout[(size_t)(tbase + s)*CDI + d] = p + sxD[s][ch];
        }
    }
}

// ---------------------------------------------------------------------------
// Gate + direction merge -> fp16 hi/lo comb (out_proj split operand)
// ---------------------------------------------------------------------------
__global__ void __launch_bounds__(256) combine_kernel()
{
    const int l0 = blockIdx.x * 32;
    const int d0 = blockIdx.y * 32;
    const int b  = blockIdx.z;

    __shared__ float zs[32][33];
    const int lane = threadIdx.x & 31;
    const int wy   = threadIdx.x >> 5;

    const float* zbase = g_xz + ((size_t)b * (2*CDI) + CDI + d0) * CL;
    for (int dd = wy; dd < 32; dd += 8)
        zs[dd][lane] = zbase[(size_t)dd * CL + l0 + lane];
    __syncthreads();

#pragma unroll
    for (int q = 0; q < 4; ++q) {
        int lr = wy + 8*q;
        int l = l0 + lr;
        size_t idx  = ((size_t)b*CL + l)*CDI + d0 + lane;
        size_t idxr = ((size_t)b*CL + (CL-1-l))*CDI + d0 + lane;
        float yf = g_y[0][idx];
        float yb = g_y[1][idxr];
        float zv = zs[lane][lr];
        float s = zv / (1.f + __expf(-zv));
        float cv = (yf + yb) * s;
        __half hb = __float2half_rn(cv);
        g_cmb_h[idx] = hb;
        g_cmb_l[idx] = __float2half_rn(cv - __half2float(hb));
    }
}

// ---------------------------------------------------------------------------
// Launcher
// ---------------------------------------------------------------------------
extern "C" void kernel_launch(void* const* d_in, const int* in_sizes, int n_in,
                              void* d_out, int out_size)
{
    (void)in_sizes; (void)n_in; (void)out_size;

    const float* hidden  = (const float*)d_in[0];
    const float* in_w    = (const float*)d_in[1];
    const float* conv_w  = (const float*)d_in[2];
    const float* conv_b  = (const float*)d_in[3];
    const float* xproj_w = (const float*)d_in[4];
    const float* dtw     = (const float*)d_in[5];
    const float* dtb     = (const float*)d_in[6];
    const float* A_log   = (const float*)d_in[7];
    const float* Dv      = (const float*)d_in[8];
    const float* conv_w2 = (const float*)d_in[9];
    const float* conv_b2 = (const float*)d_in[10];
    const float* xproj_w2= (const float*)d_in[11];
    const float* dtw2    = (const float*)d_in[12];
    const float* dtb2    = (const float*)d_in[13];
    const float* A_log2  = (const float*)d_in[14];
    const float* Dv2     = (const float*)d_in[15];
    const float* out_w   = (const float*)d_in[16];

    void *p_xz, *p_dbl;
    void *p_hid_h, *p_hid_l, *p_w1, *p_w2, *p_wx, *p_xth, *p_xtl, *p_cmb_h, *p_cmb_l;
    cudaGetSymbolAddress(&p_xz, g_xz);
    cudaGetSymbolAddress(&p_dbl, g_dbl);
    cudaGetSymbolAddress(&p_hid_h, g_hid_h);
    cudaGetSymbolAddress(&p_hid_l, g_hid_l);
    cudaGetSymbolAddress(&p_w1, g_w1);
    cudaGetSymbolAddress(&p_w2, g_w2);
    cudaGetSymbolAddress(&p_wx, g_wx);
    cudaGetSymbolAddress(&p_xth, g_xth);
    cudaGetSymbolAddress(&p_xtl, g_xtl);
    cudaGetSymbolAddress(&p_cmb_h, g_cmb_h);
    cudaGetSymbolAddress(&p_cmb_l, g_cmb_l);

    cudaFuncSetAttribute(gemm_f16_kernel<0>,
                         cudaFuncAttributeMaxDynamicSharedMemorySize, GF_SMEM);
    cudaFuncSetAttribute(gemm_f16_kernel<1>,
                         cudaFuncAttributeMaxDynamicSharedMemorySize, GF_SMEM);

    // 0) operand packing
    split2_kernel<<<1024, 256>>>(hidden, (__half*)p_hid_h, (__half*)p_hid_l, CB*CL*CDM/4);
    tof16_kernel<<<512, 256>>>(in_w, (__half*)p_w1, 2*CDI*CDM/4);
    tof16_kernel<<<512, 256>>>(out_w, (__half*)p_w2, CDM*CDI/4);
    padw_kernel<<<512, 256>>>(xproj_w, xproj_w2);

    // 1) in_proj: A = w1 (single), B = hidden (split).  M=3072, N=4096, K=768
    gemm_f16_kernel<0><<<dim3(CL/128, (2*CDI)/128, CB), 256, GF_SMEM>>>(
        (const __half*)p_w1, (const __half*)p_hid_l, (const __half*)p_hid_h,
        (float*)p_xz, CL, CDM,
        0, (long long)CL * CDM, (long long)(2*CDI) * CL, CDM / 64);

    // 2) conv + SiLU + transpose -> fp16 hi/lo xt
    conv_silu_kernel<<<dim3(CL/128, CDI/32, 2*CB), 256>>>(
        conv_w, conv_b, conv_w2, conv_b2);

    // 3) xproj: A = xt (split), B = wx (single).  M=8192 rows, N=80(pad128), K=1536
    gemm_f16_kernel<1><<<dim3(1, (CB*CL)/128, 2), 256, GF_SMEM>>>(
        (const __half*)p_xth, (const __half*)p_xtl, (const __half*)p_wx,
        (float*)p_dbl, CPROJ, CDI,
        (long long)CB*CL*CDI, (long long)128*CDI, (long long)CB*CL*CPROJ, CDI / 64);

    // 4) dtproj + softplus -> delta
    dtproj_kernel<<<dim3((CB*CL)/64, CDI/128, 2), 256>>>(dtw, dtb, dtw2, dtb2);

    // 5) selective scan
    scan_kernel<<<dim3(CDI/16, CB, 2), 256>>>(A_log, Dv, A_log2, Dv2);

    // 6) gate + direction merge -> fp16 hi/lo comb
    combine_kernel<<<dim3(CL/32, CDI/32, CB), 256>>>();

    // 7) out_proj: A = comb (split), B = w2 (single).  M=8192, N=768, K=1536
    gemm_f16_kernel<1><<<dim3(CDM/128, (CB*CL)/128, 1), 256, GF_SMEM>>>(
        (const __half*)p_cmb_h, (const __half*)p_cmb_l, (const __half*)p_w2,
        (float*)d_out, CDM, CDI,
        0, 0, 0, CDI / 64);
}